// round 9
// baseline (speedup 1.0000x reference)
#include <cuda_runtime.h>

#define T_LEN 1024
#define B_SZ  128
#define D_IN  32
#define H_DIM 64
#define W_DIM 128
#define C_DIM 33     // D_IN + 1
#define O_DIM 2112   // H_DIM * C_DIM
#define O_MAIN 2048  // main (uniform) part of layer-3 outputs
#define BA    4      // batches per CTA
#define NCTA  (B_SZ / BA)   // 32
#define NTHR  512

// Transposed copy of vW2 rows [0, 2048): g_vW2T[k * 2048 + o] = vW2[o * 128 + k]
__device__ float g_vW2T[W_DIM * O_MAIN];

__global__ void cde_transpose_kernel(const float* __restrict__ vW2) {
    int idx = blockIdx.x * blockDim.x + threadIdx.x;
    if (idx < W_DIM * O_MAIN) {
        int k = idx >> 11;     // / 2048
        int o = idx & 2047;
        g_vW2T[idx] = vW2[o * W_DIM + k];
    }
}

struct __align__(16) Smem {
    float vW0p[W_DIM * 66];   // [j][paired w[1..64]]; stride 66 (33 u64, odd) -> LDS.64 conflict-free
    float vW0c[W_DIM];        // w[j][0] (the t column)
    float vW1[W_DIM * 130];   // [j][k], stride 130 (65 u64, odd) -> LDS.64 conflict-free
    float vb0[W_DIM];
    float vb1[W_DIM];
    float vb2[O_DIM];
    float vbuf[BA][O_DIM];    // v (tanh outputs), per batch
    float z1[BA][W_DIM];
    float z2[BA][W_DIM];
    float z2q[W_DIM][BA];     // z2 "quad": [k] -> (b0,b1,b2,b3) for layer-3 broadcast
    float yhat1[BA][H_DIM];
    float dxv[BA][C_DIM];
    float cury[BA][D_IN];
    float red[BA][H_DIM];
};

typedef unsigned long long u64;

__device__ __forceinline__ void ffma2(u64& d, u64 a, u64 b) {
    // d.lo += a.lo*b.lo ; d.hi += a.hi*b.hi  (packed fp32x2 FMA, sm_100+)
    asm("fma.rn.f32x2 %0, %1, %2, %0;" : "+l"(d) : "l"(a), "l"(b));
}
__device__ __forceinline__ u64 pack2(float x, float y) {
    u64 r;
    asm("mov.b64 %0, {%1, %2};" : "=l"(r) : "f"(x), "f"(y));
    return r;
}
__device__ __forceinline__ float2 unpack2(u64 v) {
    float2 r;
    asm("mov.b64 {%0, %1}, %2;" : "=f"(r.x), "=f"(r.y) : "l"(v));
    return r;
}

__device__ __forceinline__ float lipswish_f(float x) {
    float sg = __fdividef(1.0f, 1.0f + __expf(-x));
    return 0.909f * x * sg;
}

__device__ __forceinline__ float tanh_f(float x) {
    float e = __expf(2.0f * x);
    return 1.0f - __fdividef(2.0f, e + 1.0f);
}

// vbuf = tanh(vW2 @ lipswish(vW1 @ lipswish(vW0 @ [t, yhat1] + vb0) + vb1) + vb2)
// for the BA=4 batches handled by this CTA. All 512 threads participate.
__device__ __forceinline__ void vf_eval(Smem* sm, int tid, float t1,
                                        const float* __restrict__ vW2) {
    const int bb = tid >> 7;   // 0..3
    const int j  = tid & 127;

    // ---- layer 1: (65 -> 128), paired FFMA2 over the 64 yh inputs ----
    {
        const u64* wp = (const u64*)&sm->vW0p[j * 66];
        const u64* yp = (const u64*)sm->yhat1[bb];
        u64 acc[4] = {0ull, 0ull, 0ull, 0ull};
        #pragma unroll
        for (int p = 0; p < 32; p++) ffma2(acc[p & 3], wp[p], yp[p]);
        float2 s0 = unpack2(acc[0]), s1 = unpack2(acc[1]);
        float2 s2 = unpack2(acc[2]), s3 = unpack2(acc[3]);
        float a = sm->vb0[j] + t1 * sm->vW0c[j]
                + ((s0.x + s0.y) + (s1.x + s1.y))
                + ((s2.x + s2.y) + (s3.x + s3.y));
        sm->z1[bb][j] = lipswish_f(a);
    }
    __syncthreads();

    // ---- layer 2: (128 -> 128), paired ----
    {
        const u64* wp = (const u64*)&sm->vW1[j * 130];
        const u64* zp = (const u64*)sm->z1[bb];
        u64 acc[4] = {0ull, 0ull, 0ull, 0ull};
        #pragma unroll
        for (int p = 0; p < 64; p++) ffma2(acc[p & 3], wp[p], zp[p]);
        float2 s0 = unpack2(acc[0]), s1 = unpack2(acc[1]);
        float2 s2 = unpack2(acc[2]), s3 = unpack2(acc[3]);
        float a = sm->vb1[j]
                + ((s0.x + s0.y) + (s1.x + s1.y))
                + ((s2.x + s2.y) + (s3.x + s3.y));
        float v = lipswish_f(a);
        sm->z2[bb][j]  = v;    // for tail
        sm->z2q[j][bb] = v;    // quad layout for main layer 3
    }
    __syncthreads();

    // ---- layer 3 main: outputs [0, 2048), 4 per thread x 4 batches.
    // One LDG.128 of weights feeds 8 FFMA2 (4 batches x 4 outputs).
    {
        u64 acc[8];   // acc[2*b + p]: outputs (4t+2p, 4t+2p+1) for batch b
        #pragma unroll
        for (int i = 0; i < 8; i++) acc[i] = 0ull;

        const float* wbase = g_vW2T + 4 * tid;
        #pragma unroll 4
        for (int k = 0; k < W_DIM; k++) {
            ulonglong2 w = *(const ulonglong2*)(wbase + (size_t)k * O_MAIN);
            float4 zq = *(const float4*)sm->z2q[k];     // broadcast LDS.128
            u64 zz0 = pack2(zq.x, zq.x);
            u64 zz1 = pack2(zq.y, zq.y);
            u64 zz2 = pack2(zq.z, zq.z);
            u64 zz3 = pack2(zq.w, zq.w);
            ffma2(acc[0], w.x, zz0); ffma2(acc[1], w.y, zz0);
            ffma2(acc[2], w.x, zz1); ffma2(acc[3], w.y, zz1);
            ffma2(acc[4], w.x, zz2); ffma2(acc[5], w.y, zz2);
            ffma2(acc[6], w.x, zz3); ffma2(acc[7], w.y, zz3);
        }
        // epilogue: bias + tanh + store (STS.128 per batch)
        const int o = 4 * tid;
        float b0v = sm->vb2[o + 0], b1v = sm->vb2[o + 1];
        float b2v = sm->vb2[o + 2], b3v = sm->vb2[o + 3];
        #pragma unroll
        for (int b = 0; b < BA; b++) {
            float2 r0 = unpack2(acc[2 * b + 0]);
            float2 r1 = unpack2(acc[2 * b + 1]);
            float4 res;
            res.x = tanh_f(r0.x + b0v);
            res.y = tanh_f(r0.y + b1v);
            res.z = tanh_f(r1.x + b2v);
            res.w = tanh_f(r1.y + b3v);
            *(float4*)&sm->vbuf[b][o] = res;
        }
    }

    // ---- layer 3 tail: outputs [2048, 2112), warp-per-4-outputs reduction ----
    {
        const int w = tid >> 5, lane = tid & 31;   // 16 warps
        float4 zz[BA];
        #pragma unroll
        for (int b = 0; b < BA; b++) zz[b] = *(const float4*)&sm->z2[b][4 * lane];
        #pragma unroll
        for (int i = 0; i < 4; i++) {
            int o = O_MAIN + w * 4 + i;
            float4 wv = *(const float4*)(vW2 + (size_t)o * W_DIM + 4 * lane);
            #pragma unroll
            for (int b = 0; b < BA; b++) {
                float a = wv.x * zz[b].x + wv.y * zz[b].y
                        + wv.z * zz[b].z + wv.w * zz[b].w;
                #pragma unroll
                for (int off = 16; off; off >>= 1)
                    a += __shfl_xor_sync(0xffffffffu, a, off);
                if (lane == 0) sm->vbuf[b][o] = tanh_f(a + sm->vb2[o]);
            }
        }
    }
    __syncthreads();
}

__global__ void __launch_bounds__(NTHR, 1) cde_kernel(
    const float* __restrict__ ts,  const float* __restrict__ ys,
    const float* __restrict__ iW0, const float* __restrict__ ib0,
    const float* __restrict__ iW1, const float* __restrict__ ib1,
    const float* __restrict__ iW2, const float* __restrict__ ib2,
    const float* __restrict__ vW0, const float* __restrict__ vb0,
    const float* __restrict__ vW1, const float* __restrict__ vb1,
    const float* __restrict__ vW2, const float* __restrict__ vb2,
    const float* __restrict__ rW,  const float* __restrict__ rb,
    float* __restrict__ out)
{
    extern __shared__ float smraw[];
    Smem* sm = reinterpret_cast<Smem*>(smraw);
    const int tid = threadIdx.x;
    const int b0  = blockIdx.x * BA;   // four batch elements per CTA

    // ---- stage weights into smem (paired layouts) ----
    for (int i = tid; i < W_DIM * 65; i += NTHR) {
        int j = i / 65, c = i % 65;
        if (c == 0) sm->vW0c[j] = vW0[i];
        else        sm->vW0p[j * 66 + (c - 1)] = vW0[i];
    }
    for (int i = tid; i < W_DIM * W_DIM; i += NTHR) {
        int j = i >> 7, k = i & 127;
        sm->vW1[j * 130 + k] = vW1[i];
    }
    if (tid < W_DIM) { sm->vb0[tid] = vb0[tid]; sm->vb1[tid] = vb1[tid]; }
    for (int i = tid; i < O_DIM; i += NTHR) sm->vb2[i] = vb2[i];

    // initial input x0 = [ts[0], ys[b,0,:]]  (reuse dxv buffer)
    if (tid < BA * C_DIM) {
        int bb = tid / C_DIM, c = tid % C_DIM;
        sm->dxv[bb][c] = (c == 0) ? ts[0]
                                  : ys[(size_t)(b0 + bb) * T_LEN * D_IN + (c - 1)];
    }
    if (tid < BA * D_IN) {
        int bb = tid >> 5, c = tid & 31;
        sm->cury[bb][c] = ys[(size_t)(b0 + bb) * T_LEN * D_IN + c];
    }
    __syncthreads();

    // ---- initial MLP: relu(iW0 x + ib0) -> relu(iW1 . + ib1) -> iW2 . + ib2 ----
    {
        int bb = tid >> 7, j = tid & 127;
        float a = ib0[j];
        #pragma unroll
        for (int i = 0; i < C_DIM; i++) a += sm->dxv[bb][i] * iW0[j * C_DIM + i];
        sm->z1[bb][j] = fmaxf(a, 0.f);
    }
    __syncthreads();
    {
        int bb = tid >> 7, j = tid & 127;
        float a = ib1[j];
        #pragma unroll 8
        for (int k = 0; k < W_DIM; k++) a += sm->z1[bb][k] * iW1[j * W_DIM + k];
        sm->z2[bb][j] = fmaxf(a, 0.f);
    }
    __syncthreads();

    float y = 0.f, yhat = 0.f, sdot = 0.f;
    if (tid < BA * H_DIM) {
        int bb = tid >> 6, h = tid & 63;
        float a = ib2[h];
        #pragma unroll 8
        for (int k = 0; k < W_DIM; k++) a += sm->z2[bb][k] * iW2[h * W_DIM + k];
        y = a; yhat = a;
        sm->yhat1[bb][h] = a;
    }
    __syncthreads();

    // v0 = vf(ts[0], y0)
    vf_eval(sm, tid, ts[0], vW2);

    // ---- scan over 1023 steps ----
    float tprev = ts[0];
    for (int t = 1; t < T_LEN; t++) {
        float t1 = __ldg(&ts[t]);

        // dx = x[t] - x[t-1]
        if (tid < BA * C_DIM) {
            int bb = tid / C_DIM, c = tid % C_DIM;
            if (c == 0) {
                sm->dxv[bb][0] = t1 - tprev;
            } else {
                float nv = ys[(size_t)(b0 + bb) * T_LEN * D_IN + (size_t)t * D_IN + (c - 1)];
                sm->dxv[bb][c] = nv - sm->cury[bb][c - 1];
                sm->cury[bb][c - 1] = nv;
            }
        }
        tprev = t1;
        __syncthreads();

        // s = v . dx ; yhat1 = 2y - yhat + s
        if (tid < BA * H_DIM) {
            int bb = tid >> 6, h = tid & 63;
            const float* vp = &sm->vbuf[bb][h * C_DIM];
            const float* dp = sm->dxv[bb];
            float a = 0.f;
            #pragma unroll
            for (int c = 0; c < C_DIM; c++) a += vp[c] * dp[c];
            sdot = a;
            float yh1 = 2.f * y - yhat + a;
            yhat = yh1;
            sm->yhat1[bb][h] = yh1;
        }
        __syncthreads();

        // v1 = vf(t1, yhat1)  (overwrites vbuf)
        vf_eval(sm, tid, t1, vW2);

        // y += 0.5 * (s + v1 . dx)
        if (tid < BA * H_DIM) {
            int bb = tid >> 6, h = tid & 63;
            const float* vp = &sm->vbuf[bb][h * C_DIM];
            const float* dp = sm->dxv[bb];
            float a = 0.f;
            #pragma unroll
            for (int c = 0; c < C_DIM; c++) a += vp[c] * dp[c];
            y += 0.5f * (sdot + a);
        }
        __syncthreads();   // protects dxv/cury for next iteration's writes
    }

    // ---- readout: out[b] = y . rW + rb ----
    if (tid < BA * H_DIM) {
        int bb = tid >> 6, h = tid & 63;
        sm->red[bb][h] = y * rW[h];
    }
    __syncthreads();
    if (tid < BA) {
        float a = rb[0];
        #pragma unroll
        for (int h = 0; h < H_DIM; h++) a += sm->red[tid][h];
        out[b0 + tid] = a;
    }
}

extern "C" void kernel_launch(void* const* d_in, const int* in_sizes, int n_in,
                              void* d_out, int out_size) {
    (void)in_sizes; (void)n_in; (void)out_size;
    const float* ts  = (const float*)d_in[0];
    const float* ys  = (const float*)d_in[1];
    const float* iW0 = (const float*)d_in[2];
    const float* ib0 = (const float*)d_in[3];
    const float* iW1 = (const float*)d_in[4];
    const float* ib1 = (const float*)d_in[5];
    const float* iW2 = (const float*)d_in[6];
    const float* ib2 = (const float*)d_in[7];
    const float* vW0 = (const float*)d_in[8];
    const float* vb0 = (const float*)d_in[9];
    const float* vW1 = (const float*)d_in[10];
    const float* vb1 = (const float*)d_in[11];
    const float* vW2 = (const float*)d_in[12];
    const float* vb2 = (const float*)d_in[13];
    const float* rW  = (const float*)d_in[14];
    const float* rb  = (const float*)d_in[15];
    float* out = (float*)d_out;

    cudaFuncSetAttribute(cde_kernel, cudaFuncAttributeMaxDynamicSharedMemorySize,
                         (int)sizeof(Smem));

    cde_transpose_kernel<<<(W_DIM * O_MAIN + 255) / 256, 256>>>(vW2);
    cde_kernel<<<NCTA, NTHR, sizeof(Smem)>>>(
        ts, ys, iW0, ib0, iW1, ib1, iW2, ib2,
        vW0, vb0, vW1, vb1, vW2, vb2, rW, rb, out);
}

// round 10
// speedup vs baseline: 1.4481x; 1.4481x over previous
#include <cuda_runtime.h>

#define T_LEN 1024
#define B_SZ  128
#define D_IN  32
#define H_DIM 64
#define W_DIM 128
#define C_DIM 33     // D_IN + 1
#define O_DIM 2112   // H_DIM * C_DIM
#define O_MAIN 2048  // main (uniform) part of layer-3 outputs
#define BA    2      // batches per CTA
#define NCTA  (B_SZ / BA)   // 64
#define NTHR  512

// Transposed copy of vW2 rows [0, 2048): g_vW2T[k * 2048 + o] = vW2[o * 128 + k]
__device__ float g_vW2T[W_DIM * O_MAIN];

__global__ void cde_transpose_kernel(const float* __restrict__ vW2) {
    int idx = blockIdx.x * blockDim.x + threadIdx.x;
    if (idx < W_DIM * O_MAIN) {
        int k = idx >> 11;     // / 2048
        int o = idx & 2047;
        g_vW2T[idx] = vW2[o * W_DIM + k];
    }
}

struct __align__(16) Smem {
    // layer-1 weights: row j has halves at [0,32) and [34,66) within stride-68 rows
    float vW0p[W_DIM * 68];
    float vW0c[W_DIM];        // w[j][0] (the t column)
    // layer-2 weights: row j has halves at [0,64) and [66,130) within stride-132 rows
    float vW1[W_DIM * 132];
    float vb0[W_DIM];
    float vb1[W_DIM];
    float vb2[O_DIM];
    float vbuf[BA][O_DIM];    // v (tanh outputs), per batch
    float z1[BA][W_DIM];
    float z2[BA][W_DIM];      // plain copy (for tail)
    float z2p[W_DIM][2];      // [k] -> (z_b0, z_b1) for layer-3 broadcast
    float yhat1[BA][H_DIM];
    float dxv[BA][C_DIM];
    float cury[BA][D_IN];
    float red[BA][H_DIM];
};

typedef unsigned long long u64;

__device__ __forceinline__ void ffma2(u64& d, u64 a, u64 b) {
    // d.lo += a.lo*b.lo ; d.hi += a.hi*b.hi  (packed fp32x2 FMA, sm_100+)
    asm("fma.rn.f32x2 %0, %1, %2, %0;" : "+l"(d) : "l"(a), "l"(b));
}
__device__ __forceinline__ u64 pack2(float x, float y) {
    u64 r;
    asm("mov.b64 %0, {%1, %2};" : "=l"(r) : "f"(x), "f"(y));
    return r;
}
__device__ __forceinline__ float2 unpack2(u64 v) {
    float2 r;
    asm("mov.b64 {%0, %1}, %2;" : "=f"(r.x), "=f"(r.y) : "l"(v));
    return r;
}

__device__ __forceinline__ float lipswish_f(float x) {
    float sg = __fdividef(1.0f, 1.0f + __expf(-x));
    return 0.909f * x * sg;
}

__device__ __forceinline__ float tanh_f(float x) {
    float e = __expf(2.0f * x);
    return 1.0f - __fdividef(2.0f, e + 1.0f);
}

// vbuf = tanh(vW2 @ lipswish(vW1 @ lipswish(vW0 @ [t, yhat1] + vb0) + vb1) + vb2)
// for both batches handled by this CTA. All 512 threads participate.
__device__ __forceinline__ void vf_eval(Smem* sm, int tid, float t1,
                                        const float* __restrict__ vW2) {
    const int pair = tid >> 1;       // work item 0..255
    const int half = tid & 1;        // k-split half
    const int bb = pair >> 7;        // batch
    const int j  = pair & 127;       // neuron

    // ---- layer 1: (65 -> 128); each half does 32 of the 64 yh inputs ----
    {
        const u64* wp = (const u64*)&sm->vW0p[j * 68 + half * 34];
        const u64* yp = (const u64*)&sm->yhat1[bb][half * 32];
        u64 a0 = 0ull, a1 = 0ull;
        #pragma unroll
        for (int p = 0; p < 16; p += 2) {
            ffma2(a0, wp[p],     yp[p]);
            ffma2(a1, wp[p + 1], yp[p + 1]);
        }
        float2 s0 = unpack2(a0), s1 = unpack2(a1);
        float part = (s0.x + s0.y) + (s1.x + s1.y);
        part += __shfl_xor_sync(0xffffffffu, part, 1);
        if (half == 0) {
            float a = sm->vb0[j] + t1 * sm->vW0c[j] + part;
            sm->z1[bb][j] = lipswish_f(a);
        }
    }
    __syncthreads();

    // ---- layer 2: (128 -> 128); each half does 64 of the 128 inputs ----
    {
        const u64* wp = (const u64*)&sm->vW1[j * 132 + half * 66];
        const u64* zp = (const u64*)&sm->z1[bb][half * 64];
        u64 a0 = 0ull, a1 = 0ull, a2 = 0ull, a3 = 0ull;
        #pragma unroll
        for (int p = 0; p < 32; p += 4) {
            ffma2(a0, wp[p],     zp[p]);
            ffma2(a1, wp[p + 1], zp[p + 1]);
            ffma2(a2, wp[p + 2], zp[p + 2]);
            ffma2(a3, wp[p + 3], zp[p + 3]);
        }
        float2 s0 = unpack2(a0), s1 = unpack2(a1);
        float2 s2 = unpack2(a2), s3 = unpack2(a3);
        float part = ((s0.x + s0.y) + (s1.x + s1.y))
                   + ((s2.x + s2.y) + (s3.x + s3.y));
        part += __shfl_xor_sync(0xffffffffu, part, 1);
        if (half == 0) {
            float v = lipswish_f(sm->vb1[j] + part);
            sm->z2[bb][j]   = v;   // for tail
            sm->z2p[j][bb]  = v;   // pair layout for main loop
        }
    }
    __syncthreads();

    // ---- layer 3 main: outputs [0, 2048), 4 per thread x 2 batches.
    // One LDG.128 of weights feeds 4 FFMA2 (2 batches x 4 outputs).
    {
        u64 acc0 = 0ull, acc1 = 0ull, acc2 = 0ull, acc3 = 0ull;
        const float* wbase = g_vW2T + 4 * tid;
        #pragma unroll 4
        for (int k = 0; k < W_DIM; k++) {
            ulonglong2 w = *(const ulonglong2*)(wbase + (size_t)k * O_MAIN);
            float2 z = *(const float2*)sm->z2p[k];   // broadcast LDS.64
            u64 zz0 = pack2(z.x, z.x);
            u64 zz1 = pack2(z.y, z.y);
            ffma2(acc0, w.x, zz0); ffma2(acc1, w.y, zz0);
            ffma2(acc2, w.x, zz1); ffma2(acc3, w.y, zz1);
        }
        const int o = 4 * tid;
        float b0v = sm->vb2[o + 0], b1v = sm->vb2[o + 1];
        float b2v = sm->vb2[o + 2], b3v = sm->vb2[o + 3];
        {
            float2 r0 = unpack2(acc0), r1 = unpack2(acc1);
            float4 res;
            res.x = tanh_f(r0.x + b0v);
            res.y = tanh_f(r0.y + b1v);
            res.z = tanh_f(r1.x + b2v);
            res.w = tanh_f(r1.y + b3v);
            *(float4*)&sm->vbuf[0][o] = res;
        }
        {
            float2 r0 = unpack2(acc2), r1 = unpack2(acc3);
            float4 res;
            res.x = tanh_f(r0.x + b0v);
            res.y = tanh_f(r0.y + b1v);
            res.z = tanh_f(r1.x + b2v);
            res.w = tanh_f(r1.y + b3v);
            *(float4*)&sm->vbuf[1][o] = res;
        }
    }

    // ---- layer 3 tail: outputs [2048, 2112), 16 warps x 4 outputs ----
    {
        const int w = tid >> 5, lane = tid & 31;
        float4 zz0 = *(const float4*)&sm->z2[0][4 * lane];
        float4 zz1 = *(const float4*)&sm->z2[1][4 * lane];
        #pragma unroll
        for (int i = 0; i < 4; i++) {
            int o = O_MAIN + w * 4 + i;
            float4 wv = *(const float4*)(vW2 + (size_t)o * W_DIM + 4 * lane);
            float a0 = wv.x * zz0.x + wv.y * zz0.y + wv.z * zz0.z + wv.w * zz0.w;
            float a1 = wv.x * zz1.x + wv.y * zz1.y + wv.z * zz1.z + wv.w * zz1.w;
            #pragma unroll
            for (int off = 16; off; off >>= 1) {
                a0 += __shfl_xor_sync(0xffffffffu, a0, off);
                a1 += __shfl_xor_sync(0xffffffffu, a1, off);
            }
            if (lane == 0) {
                float b = sm->vb2[o];
                sm->vbuf[0][o] = tanh_f(a0 + b);
                sm->vbuf[1][o] = tanh_f(a1 + b);
            }
        }
    }
    __syncthreads();
}

__global__ void __launch_bounds__(NTHR, 1) cde_kernel(
    const float* __restrict__ ts,  const float* __restrict__ ys,
    const float* __restrict__ iW0, const float* __restrict__ ib0,
    const float* __restrict__ iW1, const float* __restrict__ ib1,
    const float* __restrict__ iW2, const float* __restrict__ ib2,
    const float* __restrict__ vW0, const float* __restrict__ vb0,
    const float* __restrict__ vW1, const float* __restrict__ vb1,
    const float* __restrict__ vW2, const float* __restrict__ vb2,
    const float* __restrict__ rW,  const float* __restrict__ rb,
    float* __restrict__ out)
{
    extern __shared__ float smraw[];
    Smem* sm = reinterpret_cast<Smem*>(smraw);
    const int tid = threadIdx.x;
    const int b0  = blockIdx.x * BA;   // two batch elements per CTA

    // ---- stage weights into smem (split-half layouts) ----
    for (int i = tid; i < W_DIM * 65; i += NTHR) {
        int j = i / 65, c = i % 65;
        if (c == 0) sm->vW0c[j] = vW0[i];
        else {
            int cc = c - 1;
            sm->vW0p[j * 68 + (cc >> 5) * 34 + (cc & 31)] = vW0[i];
        }
    }
    for (int i = tid; i < W_DIM * W_DIM; i += NTHR) {
        int j = i >> 7, k = i & 127;
        sm->vW1[j * 132 + (k >> 6) * 66 + (k & 63)] = vW1[i];
    }
    if (tid < W_DIM) { sm->vb0[tid] = vb0[tid]; sm->vb1[tid] = vb1[tid]; }
    for (int i = tid; i < O_DIM; i += NTHR) sm->vb2[i] = vb2[i];

    // initial input x0 = [ts[0], ys[b,0,:]]  (reuse dxv buffer)
    if (tid < BA * C_DIM) {
        int bb = tid / C_DIM, c = tid % C_DIM;
        sm->dxv[bb][c] = (c == 0) ? ts[0]
                                  : ys[(size_t)(b0 + bb) * T_LEN * D_IN + (c - 1)];
    }
    if (tid < BA * D_IN) {
        int bb = tid >> 5, c = tid & 31;
        sm->cury[bb][c] = ys[(size_t)(b0 + bb) * T_LEN * D_IN + c];
    }
    __syncthreads();

    // ---- initial MLP (one-time; tid<256 active) ----
    if (tid < 256) {
        int bb = tid >> 7, j = tid & 127;
        float a = ib0[j];
        #pragma unroll
        for (int i = 0; i < C_DIM; i++) a += sm->dxv[bb][i] * iW0[j * C_DIM + i];
        sm->z1[bb][j] = fmaxf(a, 0.f);
    }
    __syncthreads();
    if (tid < 256) {
        int bb = tid >> 7, j = tid & 127;
        float a = ib1[j];
        #pragma unroll 8
        for (int k = 0; k < W_DIM; k++) a += sm->z1[bb][k] * iW1[j * W_DIM + k];
        sm->z2[bb][j] = fmaxf(a, 0.f);
    }
    __syncthreads();

    float y = 0.f, yhat = 0.f, sdot = 0.f;
    if (tid < BA * H_DIM) {
        int bb = tid >> 6, h = tid & 63;
        float a = ib2[h];
        #pragma unroll 8
        for (int k = 0; k < W_DIM; k++) a += sm->z2[bb][k] * iW2[h * W_DIM + k];
        y = a; yhat = a;
        sm->yhat1[bb][h] = a;
    }
    __syncthreads();

    // v0 = vf(ts[0], y0)
    vf_eval(sm, tid, ts[0], vW2);

    // ---- scan over 1023 steps ----
    float tprev = ts[0];
    for (int t = 1; t < T_LEN; t++) {
        float t1 = __ldg(&ts[t]);

        // dx = x[t] - x[t-1]
        if (tid < BA * C_DIM) {
            int bb = tid / C_DIM, c = tid % C_DIM;
            if (c == 0) {
                sm->dxv[bb][0] = t1 - tprev;
            } else {
                float nv = ys[(size_t)(b0 + bb) * T_LEN * D_IN + (size_t)t * D_IN + (c - 1)];
                sm->dxv[bb][c] = nv - sm->cury[bb][c - 1];
                sm->cury[bb][c - 1] = nv;
            }
        }
        tprev = t1;
        __syncthreads();

        // s = v . dx ; yhat1 = 2y - yhat + s
        if (tid < BA * H_DIM) {
            int bb = tid >> 6, h = tid & 63;
            const float* vp = &sm->vbuf[bb][h * C_DIM];
            const float* dp = sm->dxv[bb];
            float a = 0.f;
            #pragma unroll
            for (int c = 0; c < C_DIM; c++) a += vp[c] * dp[c];
            sdot = a;
            float yh1 = 2.f * y - yhat + a;
            yhat = yh1;
            sm->yhat1[bb][h] = yh1;
        }
        __syncthreads();

        // v1 = vf(t1, yhat1)  (overwrites vbuf; ends with __syncthreads)
        vf_eval(sm, tid, t1, vW2);

        // y += 0.5 * (s + v1 . dx)
        if (tid < BA * H_DIM) {
            int bb = tid >> 6, h = tid & 63;
            const float* vp = &sm->vbuf[bb][h * C_DIM];
            const float* dp = sm->dxv[bb];
            float a = 0.f;
            #pragma unroll
            for (int c = 0; c < C_DIM; c++) a += vp[c] * dp[c];
            y += 0.5f * (sdot + a);
        }
        __syncthreads();   // protects dxv/cury for next iteration's writes
    }

    // ---- readout: out[b] = y . rW + rb ----
    if (tid < BA * H_DIM) {
        int bb = tid >> 6, h = tid & 63;
        sm->red[bb][h] = y * rW[h];
    }
    __syncthreads();
    if (tid < BA) {
        float a = rb[0];
        #pragma unroll
        for (int h = 0; h < H_DIM; h++) a += sm->red[tid][h];
        out[b0 + tid] = a;
    }
}

extern "C" void kernel_launch(void* const* d_in, const int* in_sizes, int n_in,
                              void* d_out, int out_size) {
    (void)in_sizes; (void)n_in; (void)out_size;
    const float* ts  = (const float*)d_in[0];
    const float* ys  = (const float*)d_in[1];
    const float* iW0 = (const float*)d_in[2];
    const float* ib0 = (const float*)d_in[3];
    const float* iW1 = (const float*)d_in[4];
    const float* ib1 = (const float*)d_in[5];
    const float* iW2 = (const float*)d_in[6];
    const float* ib2 = (const float*)d_in[7];
    const float* vW0 = (const float*)d_in[8];
    const float* vb0 = (const float*)d_in[9];
    const float* vW1 = (const float*)d_in[10];
    const float* vb1 = (const float*)d_in[11];
    const float* vW2 = (const float*)d_in[12];
    const float* vb2 = (const float*)d_in[13];
    const float* rW  = (const float*)d_in[14];
    const float* rb  = (const float*)d_in[15];
    float* out = (float*)d_out;

    cudaFuncSetAttribute(cde_kernel, cudaFuncAttributeMaxDynamicSharedMemorySize,
                         (int)sizeof(Smem));

    cde_transpose_kernel<<<(W_DIM * O_MAIN + 255) / 256, 256>>>(vW2);
    cde_kernel<<<NCTA, NTHR, sizeof(Smem)>>>(
        ts, ys, iW0, ib0, iW1, ib1, iW2, ib2,
        vW0, vb0, vW1, vb1, vW2, vb2, rW, rb, out);
}

// round 11
// speedup vs baseline: 1.5121x; 1.0442x over previous
#include <cuda_runtime.h>
#include <cstdint>

#define T_LEN 1024
#define B_SZ  128
#define D_IN  32
#define H_DIM 64
#define W_DIM 128
#define C_DIM 33     // D_IN + 1
#define O_DIM 2112   // H_DIM * C_DIM
#define OSL   1056   // outputs per CTA slice (32 h * 33 c)
#define OSL_MAIN 1024
#define HSL   32     // h per CTA
#define BA    2      // batches per cluster (and per CTA)
#define NTHR  256
#define NCTA  128    // 64 clusters * 2

// Full transposed vW2: g_vW2T[k * 2112 + o] = vW2[o * 128 + k]
__device__ float g_vW2T[W_DIM * O_DIM];

__global__ void cde_transpose_kernel(const float* __restrict__ vW2) {
    int idx = blockIdx.x * blockDim.x + threadIdx.x;
    if (idx < W_DIM * O_DIM) {
        int k = idx / O_DIM, o = idx - k * O_DIM;
        g_vW2T[idx] = vW2[o * W_DIM + k];
    }
}

struct __align__(16) Smem {
    float vW0p[W_DIM * 66];   // [j][w(1..64) paired]; stride 66 -> LDS.64 conflict-free
    float vW0c[W_DIM];        // w[j][0] (t column)
    float vW1[W_DIM * 130];   // [j][k], stride 130 -> LDS.64 conflict-free
    float vb0[W_DIM];
    float vb1[W_DIM];
    float vb2s[OSL];          // bias slice for this CTA's outputs
    float vloc[BA][OSL];      // v slice (tanh outputs) per batch
    float z1[BA][W_DIM];
    float z2[BA][W_DIM];      // per-batch copy (for tail)
    float z2p[W_DIM][2];      // [k] -> (z_b0, z_b1) for main-loop broadcast
    float yh[2][BA][H_DIM];   // FULL yhat, double-buffered by step parity
    float dxv[BA][C_DIM];
    float cury[BA][D_IN];
    float red[BA][HSL];
    float pbuf[2][BA];        // readout partials (gathered at rank 0)
};

typedef unsigned long long u64;

__device__ __forceinline__ void ffma2(u64& d, u64 a, u64 b) {
    asm("fma.rn.f32x2 %0, %1, %2, %0;" : "+l"(d) : "l"(a), "l"(b));
}
__device__ __forceinline__ u64 pack2(float x, float y) {
    u64 r;
    asm("mov.b64 %0, {%1, %2};" : "=l"(r) : "f"(x), "f"(y));
    return r;
}
__device__ __forceinline__ float2 unpack2(u64 v) {
    float2 r;
    asm("mov.b64 {%0, %1}, %2;" : "=f"(r.x), "=f"(r.y) : "l"(v));
    return r;
}
__device__ __forceinline__ uint32_t s2u(const void* p) {
    uint32_t a;
    asm("{ .reg .u64 t; cvta.to.shared.u64 t, %1; cvt.u32.u64 %0, t; }"
        : "=r"(a) : "l"(p));
    return a;
}
__device__ __forceinline__ uint32_t cl_rank() {
    uint32_t r; asm("mov.u32 %0, %%cluster_ctarank;" : "=r"(r)); return r;
}
__device__ __forceinline__ void st_cluster(uint32_t addr, uint32_t rank, float v) {
    asm volatile(
        "{ .reg .b32 r; mapa.shared::cluster.u32 r, %0, %1; st.shared::cluster.f32 [r], %2; }"
        :: "r"(addr), "r"(rank), "f"(v) : "memory");
}
#define CLUSTER_SYNC() do { \
    asm volatile("barrier.cluster.arrive.aligned;" ::: "memory"); \
    asm volatile("barrier.cluster.wait.aligned;" ::: "memory"); \
} while (0)

__device__ __forceinline__ float lipswish_f(float x) {
    float sg = __fdividef(1.0f, 1.0f + __expf(-x));
    return 0.909f * x * sg;
}
__device__ __forceinline__ float tanh_f(float x) {
    float e = __expf(2.0f * x);
    return 1.0f - __fdividef(2.0f, e + 1.0f);
}

// v slice = tanh(vW2[slice] @ lipswish(vW1 @ lipswish(vW0 @ [t, yhat] + vb0) + vb1) + vb2[slice])
__device__ __forceinline__ void vf_eval(Smem* sm, int tid, int rank, float t1, int par,
                                        const float* __restrict__ vW2) {
    const int bb = tid >> 7;   // 0..1
    const int j  = tid & 127;

    // ---- layer 1: (65 -> 128), paired FFMA2 over the 64 yh inputs ----
    {
        const u64* wp = (const u64*)&sm->vW0p[j * 66];
        const u64* yp = (const u64*)sm->yh[par][bb];
        u64 acc[4] = {0ull, 0ull, 0ull, 0ull};
        #pragma unroll
        for (int p = 0; p < 32; p++) ffma2(acc[p & 3], wp[p], yp[p]);
        float2 s0 = unpack2(acc[0]), s1 = unpack2(acc[1]);
        float2 s2 = unpack2(acc[2]), s3 = unpack2(acc[3]);
        float a = sm->vb0[j] + t1 * sm->vW0c[j]
                + ((s0.x + s0.y) + (s1.x + s1.y))
                + ((s2.x + s2.y) + (s3.x + s3.y));
        sm->z1[bb][j] = lipswish_f(a);
    }
    __syncthreads();

    // ---- layer 2: (128 -> 128), paired ----
    {
        const u64* wp = (const u64*)&sm->vW1[j * 130];
        const u64* zp = (const u64*)sm->z1[bb];
        u64 acc[4] = {0ull, 0ull, 0ull, 0ull};
        #pragma unroll
        for (int p = 0; p < 64; p++) ffma2(acc[p & 3], wp[p], zp[p]);
        float2 s0 = unpack2(acc[0]), s1 = unpack2(acc[1]);
        float2 s2 = unpack2(acc[2]), s3 = unpack2(acc[3]);
        float a = sm->vb1[j]
                + ((s0.x + s0.y) + (s1.x + s1.y))
                + ((s2.x + s2.y) + (s3.x + s3.y));
        float v = lipswish_f(a);
        sm->z2[bb][j]  = v;
        sm->z2p[j][bb] = v;
    }
    __syncthreads();

    // ---- layer 3 main: slice outputs [0, 1024), 4 per thread x 2 batches ----
    {
        u64 acc0 = 0ull, acc1 = 0ull, acc2 = 0ull, acc3 = 0ull;
        const float* wbase = g_vW2T + rank * OSL + 4 * tid;
        #pragma unroll 4
        for (int k = 0; k < W_DIM; k++) {
            ulonglong2 w = *(const ulonglong2*)(wbase + (size_t)k * O_DIM);
            float2 z = *(const float2*)sm->z2p[k];   // broadcast LDS.64
            u64 zz0 = pack2(z.x, z.x);
            u64 zz1 = pack2(z.y, z.y);
            ffma2(acc0, w.x, zz0); ffma2(acc1, w.y, zz0);
            ffma2(acc2, w.x, zz1); ffma2(acc3, w.y, zz1);
        }
        const int o = 4 * tid;
        float b0v = sm->vb2s[o + 0], b1v = sm->vb2s[o + 1];
        float b2v = sm->vb2s[o + 2], b3v = sm->vb2s[o + 3];
        {
            float2 r0 = unpack2(acc0), r1 = unpack2(acc1);
            float4 res;
            res.x = tanh_f(r0.x + b0v);
            res.y = tanh_f(r0.y + b1v);
            res.z = tanh_f(r1.x + b2v);
            res.w = tanh_f(r1.y + b3v);
            *(float4*)&sm->vloc[0][o] = res;
        }
        {
            float2 r0 = unpack2(acc2), r1 = unpack2(acc3);
            float4 res;
            res.x = tanh_f(r0.x + b0v);
            res.y = tanh_f(r0.y + b1v);
            res.z = tanh_f(r1.x + b2v);
            res.w = tanh_f(r1.y + b3v);
            *(float4*)&sm->vloc[1][o] = res;
        }
    }

    // ---- layer 3 tail: slice outputs [1024, 1056), 8 warps x 4 outputs ----
    {
        const int w = tid >> 5, lane = tid & 31;
        float4 zz0 = *(const float4*)&sm->z2[0][4 * lane];
        float4 zz1 = *(const float4*)&sm->z2[1][4 * lane];
        #pragma unroll
        for (int i = 0; i < 4; i += 4) {   // one output per warp-group pass: w*4..w*4+3
            #pragma unroll
            for (int q = 0; q < 4; q++) {
                int oloc = OSL_MAIN + w * 4 + q;
                int o = rank * OSL + oloc;
                float4 wv = *(const float4*)(vW2 + (size_t)o * W_DIM + 4 * lane);
                float a0 = wv.x * zz0.x + wv.y * zz0.y + wv.z * zz0.z + wv.w * zz0.w;
                float a1 = wv.x * zz1.x + wv.y * zz1.y + wv.z * zz1.z + wv.w * zz1.w;
                #pragma unroll
                for (int off = 16; off; off >>= 1) {
                    a0 += __shfl_xor_sync(0xffffffffu, a0, off);
                    a1 += __shfl_xor_sync(0xffffffffu, a1, off);
                }
                if (lane == 0) {
                    float b = sm->vb2s[oloc];
                    sm->vloc[0][oloc] = tanh_f(a0 + b);
                    sm->vloc[1][oloc] = tanh_f(a1 + b);
                }
            }
        }
    }
    __syncthreads();
}

__global__ void __launch_bounds__(NTHR, 1) __cluster_dims__(2, 1, 1)
cde_kernel(
    const float* __restrict__ ts,  const float* __restrict__ ys,
    const float* __restrict__ iW0, const float* __restrict__ ib0,
    const float* __restrict__ iW1, const float* __restrict__ ib1,
    const float* __restrict__ iW2, const float* __restrict__ ib2,
    const float* __restrict__ vW0, const float* __restrict__ vb0,
    const float* __restrict__ vW1, const float* __restrict__ vb1,
    const float* __restrict__ vW2, const float* __restrict__ vb2,
    const float* __restrict__ rW,  const float* __restrict__ rb,
    float* __restrict__ out)
{
    extern __shared__ float smraw[];
    Smem* sm = reinterpret_cast<Smem*>(smraw);
    const int tid  = threadIdx.x;
    const int rank = (int)cl_rank();        // 0..1
    const int b0   = (blockIdx.x >> 1) * BA;

    // ---- stage weights/biases into smem ----
    for (int i = tid; i < W_DIM * 65; i += NTHR) {
        int j = i / 65, c = i % 65;
        if (c == 0) sm->vW0c[j] = vW0[i];
        else        sm->vW0p[j * 66 + (c - 1)] = vW0[i];
    }
    for (int i = tid; i < W_DIM * W_DIM; i += NTHR) {
        int j = i >> 7, k = i & 127;
        sm->vW1[j * 130 + k] = vW1[i];
    }
    if (tid < W_DIM) { sm->vb0[tid] = vb0[tid]; sm->vb1[tid] = vb1[tid]; }
    for (int i = tid; i < OSL; i += NTHR) sm->vb2s[i] = vb2[rank * OSL + i];

    // initial input x0 = [ts[0], ys[b,0,:]] into dxv; cury = ys[b,0,:]
    if (tid < BA * C_DIM) {
        int bb = tid / C_DIM, c = tid % C_DIM;
        sm->dxv[bb][c] = (c == 0) ? ts[0]
                                  : ys[(size_t)(b0 + bb) * T_LEN * D_IN + (c - 1)];
    }
    if (tid < BA * D_IN) {
        int bb = tid >> 5, c = tid & 31;
        sm->cury[bb][c] = ys[(size_t)(b0 + bb) * T_LEN * D_IN + c];
    }
    __syncthreads();

    // ---- initial MLP (replicated per CTA, computes FULL y0) ----
    {
        int bb = tid >> 7, j = tid & 127;
        float a = ib0[j];
        #pragma unroll
        for (int i = 0; i < C_DIM; i++) a += sm->dxv[bb][i] * iW0[j * C_DIM + i];
        sm->z1[bb][j] = fmaxf(a, 0.f);
    }
    __syncthreads();
    {
        int bb = tid >> 7, j = tid & 127;
        float a = ib1[j];
        #pragma unroll 8
        for (int k = 0; k < W_DIM; k++) a += sm->z1[bb][k] * iW1[j * W_DIM + k];
        sm->z2[bb][j] = fmaxf(a, 0.f);
    }
    __syncthreads();
    if (tid < BA * H_DIM) {
        int bb = tid >> 6, h = tid & 63;
        float a = ib2[h];
        #pragma unroll 8
        for (int k = 0; k < W_DIM; k++) a += sm->z2[bb][k] * iW2[h * W_DIM + k];
        sm->yh[0][bb][h] = a;    // full y0 locally
    }
    __syncthreads();

    // slice state registers (threads 0..63): bb = tid>>5, hl = tid&31, h = 32*rank + hl
    float y = 0.f, yhat_r = 0.f, sdot = 0.f;
    if (tid < 64) {
        int bb = tid >> 5, hl = tid & 31;
        y = yhat_r = sm->yh[0][bb][HSL * rank + hl];
    }

    // v0 = vf(ts[0], y0) into vloc (slice)
    vf_eval(sm, tid, rank, ts[0], 0, vW2);

    // ---- scan over 1023 steps ----
    float tprev = ts[0];
    for (int t = 1; t < T_LEN; t++) {
        float t1 = __ldg(&ts[t]);
        int par = t & 1;

        // dx = x[t] - x[t-1]   (duplicated per CTA)
        if (tid < BA * C_DIM) {
            int bb = tid / C_DIM, c = tid % C_DIM;
            if (c == 0) {
                sm->dxv[bb][0] = t1 - tprev;
            } else {
                float nv = ys[(size_t)(b0 + bb) * T_LEN * D_IN + (size_t)t * D_IN + (c - 1)];
                sm->dxv[bb][c] = nv - sm->cury[bb][c - 1];
                sm->cury[bb][c - 1] = nv;
            }
        }
        tprev = t1;
        __syncthreads();

        // einsum1 on local slice: s = v.dx ; yhat1 = 2y - yhat + s ; push to both CTAs
        if (tid < 64) {
            int bb = tid >> 5, hl = tid & 31;
            const float* vp = &sm->vloc[bb][hl * C_DIM];
            const float* dp = sm->dxv[bb];
            float a = 0.f;
            #pragma unroll
            for (int c = 0; c < C_DIM; c++) a += vp[c] * dp[c];
            sdot = a;
            float yh1 = 2.f * y - yhat_r + a;
            yhat_r = yh1;
            uint32_t addr = s2u(&sm->yh[par][bb][HSL * rank + hl]);
            st_cluster(addr, 0, yh1);
            st_cluster(addr, 1, yh1);
        }
        CLUSTER_SYNC();   // yh[par] now complete in both CTAs

        // v1 = vf(t1, yhat1) into vloc
        vf_eval(sm, tid, rank, t1, par, vW2);

        // einsum2: y += 0.5 * (s + v1.dx)
        if (tid < 64) {
            int bb = tid >> 5, hl = tid & 31;
            const float* vp = &sm->vloc[bb][hl * C_DIM];
            const float* dp = sm->dxv[bb];
            float a = 0.f;
            #pragma unroll
            for (int c = 0; c < C_DIM; c++) a += vp[c] * dp[c];
            y += 0.5f * (sdot + a);
        }
        __syncthreads();   // protect dxv/cury before next iteration writes
    }

    // ---- readout: out[b] = sum_h y[b][h]*rW[h] + rb ----
    if (tid < 64) {
        int bb = tid >> 5, hl = tid & 31;
        sm->red[bb][hl] = y * rW[HSL * rank + hl];
    }
    __syncthreads();
    if (tid < BA) {
        float p = 0.f;
        #pragma unroll
        for (int hl = 0; hl < HSL; hl++) p += sm->red[tid][hl];
        uint32_t addr = s2u(&sm->pbuf[rank][tid]);
        st_cluster(addr, 0, p);   // gather both partials at rank 0
    }
    CLUSTER_SYNC();
    if (rank == 0 && tid < BA) {
        out[b0 + tid] = rb[0] + sm->pbuf[0][tid] + sm->pbuf[1][tid];
    }
    CLUSTER_SYNC();   // keep peer smem alive until all cluster traffic done
}

extern "C" void kernel_launch(void* const* d_in, const int* in_sizes, int n_in,
                              void* d_out, int out_size) {
    (void)in_sizes; (void)n_in; (void)out_size;
    const float* ts  = (const float*)d_in[0];
    const float* ys  = (const float*)d_in[1];
    const float* iW0 = (const float*)d_in[2];
    const float* ib0 = (const float*)d_in[3];
    const float* iW1 = (const float*)d_in[4];
    const float* ib1 = (const float*)d_in[5];
    const float* iW2 = (const float*)d_in[6];
    const float* ib2 = (const float*)d_in[7];
    const float* vW0 = (const float*)d_in[8];
    const float* vb0 = (const float*)d_in[9];
    const float* vW1 = (const float*)d_in[10];
    const float* vb1 = (const float*)d_in[11];
    const float* vW2 = (const float*)d_in[12];
    const float* vb2 = (const float*)d_in[13];
    const float* rW  = (const float*)d_in[14];
    const float* rb  = (const float*)d_in[15];
    float* out = (float*)d_out;

    cudaFuncSetAttribute(cde_kernel, cudaFuncAttributeMaxDynamicSharedMemorySize,
                         (int)sizeof(Smem));

    cde_transpose_kernel<<<(W_DIM * O_DIM + 255) / 256, 256>>>(vW2);
    cde_kernel<<<NCTA, NTHR, sizeof(Smem)>>>(
        ts, ys, iW0, ib0, iW1, ib1, iW2, ib2,
        vW0, vb0, vW1, vb1, vW2, vb2, rW, rb, out);
}

// round 12
// speedup vs baseline: 1.5400x; 1.0185x over previous
#include <cuda_runtime.h>
#include <cstdint>

#define T_LEN 1024
#define B_SZ  128
#define D_IN  32
#define H_DIM 64
#define W_DIM 128
#define C_DIM 33     // D_IN + 1
#define O_DIM 2112   // H_DIM * C_DIM
#define P_CL  4      // cluster size (output partition)
#define HSL   16     // heads per CTA slice
#define OSL   528    // outputs per CTA slice (16 h * 33 c)
#define OSL_MAIN 512 // uniform part; 16-output tail warp-reduced
#define BA    4      // batches per cluster
#define NTHR  256
#define NCTA  128    // 32 clusters * 4

// Full transposed vW2: g_vW2T[k * 2112 + o] = vW2[o * 128 + k]
__device__ float g_vW2T[W_DIM * O_DIM];

__global__ void cde_transpose_kernel(const float* __restrict__ vW2) {
    int idx = blockIdx.x * blockDim.x + threadIdx.x;
    if (idx < W_DIM * O_DIM) {
        int k = idx / O_DIM, o = idx - k * O_DIM;
        g_vW2T[idx] = vW2[o * W_DIM + k];
    }
}

struct __align__(16) Smem {
    float vW0p[W_DIM * 66];   // [j][w(1..64) paired]; stride 66 -> conflict-free LDS.64
    float vW0c[W_DIM];        // w[j][0] (t column)
    float vW1[W_DIM * 130];   // [j][k], stride 130 -> conflict-free LDS.64
    float vb0[W_DIM];
    float vb1[W_DIM];
    float vb2s[OSL];          // bias slice
    float vloc[BA][536];      // v slice per batch (pad 528->536)
    float z1[BA][132];        // stride 132 (row base 528B, 16B aligned)
    float z2c[BA][132];       // plain z2 copy (tail)
    float4 z2q[W_DIM];        // [k] -> (z_b0, z_b1, z_b2, z_b3)
    float yh[2][BA][68];      // FULL yhat, parity double-buffered (row 272B, 8B aligned)
    float dxv[BA][36];
    float cury[BA][D_IN];
    float red[BA][HSL];
    float pbuf[P_CL][BA];
};

typedef unsigned long long u64;

__device__ __forceinline__ void ffma2(u64& d, u64 a, u64 b) {
    asm("fma.rn.f32x2 %0, %1, %2, %0;" : "+l"(d) : "l"(a), "l"(b));
}
__device__ __forceinline__ u64 pack2(float x, float y) {
    u64 r;
    asm("mov.b64 %0, {%1, %2};" : "=l"(r) : "f"(x), "f"(y));
    return r;
}
__device__ __forceinline__ float2 unpack2(u64 v) {
    float2 r;
    asm("mov.b64 {%0, %1}, %2;" : "=f"(r.x), "=f"(r.y) : "l"(v));
    return r;
}
__device__ __forceinline__ uint32_t s2u(const void* p) {
    uint32_t a;
    asm("{ .reg .u64 t; cvta.to.shared.u64 t, %1; cvt.u32.u64 %0, t; }"
        : "=r"(a) : "l"(p));
    return a;
}
__device__ __forceinline__ uint32_t cl_rank() {
    uint32_t r; asm("mov.u32 %0, %%cluster_ctarank;" : "=r"(r)); return r;
}
__device__ __forceinline__ void st_cluster(uint32_t addr, uint32_t rank, float v) {
    asm volatile(
        "{ .reg .b32 r; mapa.shared::cluster.u32 r, %0, %1; st.shared::cluster.f32 [r], %2; }"
        :: "r"(addr), "r"(rank), "f"(v) : "memory");
}
#define CLUSTER_SYNC() do { \
    asm volatile("barrier.cluster.arrive.aligned;" ::: "memory"); \
    asm volatile("barrier.cluster.wait.aligned;" ::: "memory"); \
} while (0)

__device__ __forceinline__ float lipswish_f(float x) {
    float sg = __fdividef(1.0f, 1.0f + __expf(-x));
    return 0.909f * x * sg;
}
__device__ __forceinline__ float tanh_f(float x) {
    float e = __expf(2.0f * x);
    return 1.0f - __fdividef(2.0f, e + 1.0f);
}

// v slice = tanh(vW2[slice] @ lipswish(vW1 @ lipswish(vW0 @ [t, yhat] + vb0) + vb1) + vb2[slice])
// for the 4 batches of this cluster. 256 threads.
__device__ __forceinline__ void vf_eval(Smem* sm, int tid, int rank, float t1, int par,
                                        const float* __restrict__ vW2) {
    const int g = tid >> 7;    // batch group: handles batches 2g, 2g+1
    const int j = tid & 127;   // neuron

    // ---- layer 1: (65 -> 128), 2 batches per thread, weights shared ----
    {
        const u64* wp = (const u64*)&sm->vW0p[j * 66];
        const u64* y0 = (const u64*)sm->yh[par][2 * g];
        const u64* y1 = (const u64*)sm->yh[par][2 * g + 1];
        u64 a0 = 0ull, a1 = 0ull, c0 = 0ull, c1 = 0ull;
        #pragma unroll
        for (int p = 0; p < 32; p += 2) {
            u64 w0 = wp[p], w1 = wp[p + 1];
            ffma2(a0, w0, y0[p]); ffma2(a1, w1, y0[p + 1]);
            ffma2(c0, w0, y1[p]); ffma2(c1, w1, y1[p + 1]);
        }
        float2 sa0 = unpack2(a0), sa1 = unpack2(a1);
        float2 sc0 = unpack2(c0), sc1 = unpack2(c1);
        float base = sm->vb0[j] + t1 * sm->vW0c[j];
        sm->z1[2 * g][j]     = lipswish_f(base + (sa0.x + sa0.y) + (sa1.x + sa1.y));
        sm->z1[2 * g + 1][j] = lipswish_f(base + (sc0.x + sc0.y) + (sc1.x + sc1.y));
    }
    __syncthreads();

    // ---- layer 2: (128 -> 128), 2 batches per thread ----
    {
        const u64* wp = (const u64*)&sm->vW1[j * 130];
        const u64* z0 = (const u64*)sm->z1[2 * g];
        const u64* z1p = (const u64*)sm->z1[2 * g + 1];
        u64 a0 = 0ull, a1 = 0ull, c0 = 0ull, c1 = 0ull;
        #pragma unroll
        for (int p = 0; p < 64; p += 2) {
            u64 w0 = wp[p], w1 = wp[p + 1];
            ffma2(a0, w0, z0[p]);  ffma2(a1, w1, z0[p + 1]);
            ffma2(c0, w0, z1p[p]); ffma2(c1, w1, z1p[p + 1]);
        }
        float2 sa0 = unpack2(a0), sa1 = unpack2(a1);
        float2 sc0 = unpack2(c0), sc1 = unpack2(c1);
        float va = lipswish_f(sm->vb1[j] + (sa0.x + sa0.y) + (sa1.x + sa1.y));
        float vc = lipswish_f(sm->vb1[j] + (sc0.x + sc0.y) + (sc1.x + sc1.y));
        sm->z2c[2 * g][j]     = va;
        sm->z2c[2 * g + 1][j] = vc;
        float* zq = (float*)&sm->z2q[j];
        zq[2 * g]     = va;
        zq[2 * g + 1] = vc;
    }
    __syncthreads();

    // ---- layer 3 main: slice outputs [0, 512), 2 outputs x 4 batches per thread ----
    {
        const int t2 = 2 * tid;
        const float* wb = g_vW2T + rank * OSL + t2;
        u64 a00 = 0ull, a01 = 0ull, a10 = 0ull, a11 = 0ull;  // [o][b-pair]
        #pragma unroll 4
        for (int k = 0; k < W_DIM; k++) {
            float2 w = *(const float2*)(wb + (size_t)k * O_DIM);      // LDG.64
            ulonglong2 z = *(const ulonglong2*)&sm->z2q[k];           // LDS.128 broadcast
            u64 w0 = pack2(w.x, w.x), w1 = pack2(w.y, w.y);
            ffma2(a00, w0, z.x); ffma2(a01, w0, z.y);
            ffma2(a10, w1, z.x); ffma2(a11, w1, z.y);
        }
        float bias0 = sm->vb2s[t2], bias1 = sm->vb2s[t2 + 1];
        float2 r;
        r = unpack2(a00);
        sm->vloc[0][t2] = tanh_f(r.x + bias0);
        sm->vloc[1][t2] = tanh_f(r.y + bias0);
        r = unpack2(a01);
        sm->vloc[2][t2] = tanh_f(r.x + bias0);
        sm->vloc[3][t2] = tanh_f(r.y + bias0);
        r = unpack2(a10);
        sm->vloc[0][t2 + 1] = tanh_f(r.x + bias1);
        sm->vloc[1][t2 + 1] = tanh_f(r.y + bias1);
        r = unpack2(a11);
        sm->vloc[2][t2 + 1] = tanh_f(r.x + bias1);
        sm->vloc[3][t2 + 1] = tanh_f(r.y + bias1);
    }

    // ---- layer 3 tail: slice outputs [512, 528), 8 warps x 2 outputs ----
    {
        const int w = tid >> 5, lane = tid & 31;
        float4 zz0 = *(const float4*)&sm->z2c[0][4 * lane];
        float4 zz1 = *(const float4*)&sm->z2c[1][4 * lane];
        float4 zz2 = *(const float4*)&sm->z2c[2][4 * lane];
        float4 zz3 = *(const float4*)&sm->z2c[3][4 * lane];
        #pragma unroll
        for (int q = 0; q < 2; q++) {
            int ol = OSL_MAIN + w * 2 + q;
            int og = rank * OSL + ol;
            float4 wv = *(const float4*)(vW2 + (size_t)og * W_DIM + 4 * lane);
            float a0 = wv.x * zz0.x + wv.y * zz0.y + wv.z * zz0.z + wv.w * zz0.w;
            float a1 = wv.x * zz1.x + wv.y * zz1.y + wv.z * zz1.z + wv.w * zz1.w;
            float a2 = wv.x * zz2.x + wv.y * zz2.y + wv.z * zz2.z + wv.w * zz2.w;
            float a3 = wv.x * zz3.x + wv.y * zz3.y + wv.z * zz3.z + wv.w * zz3.w;
            #pragma unroll
            for (int off = 16; off; off >>= 1) {
                a0 += __shfl_xor_sync(0xffffffffu, a0, off);
                a1 += __shfl_xor_sync(0xffffffffu, a1, off);
                a2 += __shfl_xor_sync(0xffffffffu, a2, off);
                a3 += __shfl_xor_sync(0xffffffffu, a3, off);
            }
            if (lane == 0) {
                float b = sm->vb2s[ol];
                sm->vloc[0][ol] = tanh_f(a0 + b);
                sm->vloc[1][ol] = tanh_f(a1 + b);
                sm->vloc[2][ol] = tanh_f(a2 + b);
                sm->vloc[3][ol] = tanh_f(a3 + b);
            }
        }
    }
    __syncthreads();
}

__global__ void __launch_bounds__(NTHR, 1) __cluster_dims__(P_CL, 1, 1)
cde_kernel(
    const float* __restrict__ ts,  const float* __restrict__ ys,
    const float* __restrict__ iW0, const float* __restrict__ ib0,
    const float* __restrict__ iW1, const float* __restrict__ ib1,
    const float* __restrict__ iW2, const float* __restrict__ ib2,
    const float* __restrict__ vW0, const float* __restrict__ vb0,
    const float* __restrict__ vW1, const float* __restrict__ vb1,
    const float* __restrict__ vW2, const float* __restrict__ vb2,
    const float* __restrict__ rW,  const float* __restrict__ rb,
    float* __restrict__ out)
{
    extern __shared__ float smraw[];
    Smem* sm = reinterpret_cast<Smem*>(smraw);
    const int tid  = threadIdx.x;
    const int rank = (int)cl_rank();          // 0..3
    const int b0   = (blockIdx.x >> 2) * BA;  // cluster batch group

    // ---- stage weights/biases ----
    for (int i = tid; i < W_DIM * 65; i += NTHR) {
        int j = i / 65, c = i % 65;
        if (c == 0) sm->vW0c[j] = vW0[i];
        else        sm->vW0p[j * 66 + (c - 1)] = vW0[i];
    }
    for (int i = tid; i < W_DIM * W_DIM; i += NTHR) {
        int j = i >> 7, k = i & 127;
        sm->vW1[j * 130 + k] = vW1[i];
    }
    if (tid < W_DIM) { sm->vb0[tid] = vb0[tid]; sm->vb1[tid] = vb1[tid]; }
    for (int i = tid; i < OSL; i += NTHR) sm->vb2s[i] = vb2[rank * OSL + i];

    // initial x0 = [ts[0], ys[b,0,:]] into dxv; cury = ys[b,0,:]
    for (int i = tid; i < BA * C_DIM; i += NTHR) {
        int bb = i / C_DIM, c = i - bb * C_DIM;
        sm->dxv[bb][c] = (c == 0) ? ts[0]
                                  : ys[(size_t)(b0 + bb) * T_LEN * D_IN + (c - 1)];
    }
    if (tid < BA * D_IN) {
        int bb = tid >> 5, c = tid & 31;
        sm->cury[bb][c] = ys[(size_t)(b0 + bb) * T_LEN * D_IN + c];
    }
    __syncthreads();

    // ---- initial MLP (replicated per CTA, FULL y0 for all 4 batches) ----
    {
        int g = tid >> 7, j = tid & 127;
        #pragma unroll
        for (int gb = 0; gb < 2; gb++) {
            int bb = 2 * g + gb;
            float a = ib0[j];
            #pragma unroll
            for (int i = 0; i < C_DIM; i++) a += sm->dxv[bb][i] * iW0[j * C_DIM + i];
            sm->z1[bb][j] = fmaxf(a, 0.f);
        }
    }
    __syncthreads();
    {
        int g = tid >> 7, j = tid & 127;
        #pragma unroll
        for (int gb = 0; gb < 2; gb++) {
            int bb = 2 * g + gb;
            float a = ib1[j];
            #pragma unroll 8
            for (int k = 0; k < W_DIM; k++) a += sm->z1[bb][k] * iW1[j * W_DIM + k];
            sm->z2c[bb][j] = fmaxf(a, 0.f);
        }
    }
    __syncthreads();
    {
        int bb = tid >> 6, h = tid & 63;   // 256 threads = 4 b x 64 h
        float a = ib2[h];
        #pragma unroll 8
        for (int k = 0; k < W_DIM; k++) a += sm->z2c[bb][k] * iW2[h * W_DIM + k];
        sm->yh[0][bb][h] = a;
    }
    __syncthreads();

    // slice state (threads 0..63): b = tid>>4, hl = tid&15, h = 16*rank + hl
    float y = 0.f, yhat_r = 0.f, sdot = 0.f;
    if (tid < 64) {
        int bb = tid >> 4, hl = tid & 15;
        y = yhat_r = sm->yh[0][bb][HSL * rank + hl];
    }

    // v0 = vf(ts[0], y0)
    vf_eval(sm, tid, rank, ts[0], 0, vW2);

    // ---- scan over 1023 steps ----
    float tprev = ts[0];
    for (int t = 1; t < T_LEN; t++) {
        float t1 = __ldg(&ts[t]);
        int par = t & 1;

        // dx = x[t] - x[t-1]
        for (int i = tid; i < BA * C_DIM; i += NTHR) {
            int bb = i / C_DIM, c = i - bb * C_DIM;
            if (c == 0) {
                sm->dxv[bb][0] = t1 - tprev;
            } else {
                float nv = ys[(size_t)(b0 + bb) * T_LEN * D_IN + (size_t)t * D_IN + (c - 1)];
                sm->dxv[bb][c] = nv - sm->cury[bb][c - 1];
                sm->cury[bb][c - 1] = nv;
            }
        }
        tprev = t1;
        __syncthreads();

        // einsum1 on slice: s = v.dx ; yhat1 = 2y - yhat + s ; push to all 4 CTAs
        if (tid < 64) {
            int bb = tid >> 4, hl = tid & 15;
            const float* vp = &sm->vloc[bb][hl * C_DIM];
            const float* dp = sm->dxv[bb];
            float a = 0.f;
            #pragma unroll
            for (int c = 0; c < C_DIM; c++) a += vp[c] * dp[c];
            sdot = a;
            float yh1 = 2.f * y - yhat_r + a;
            yhat_r = yh1;
            uint32_t addr = s2u(&sm->yh[par][bb][HSL * rank + hl]);
            st_cluster(addr, 0, yh1);
            st_cluster(addr, 1, yh1);
            st_cluster(addr, 2, yh1);
            st_cluster(addr, 3, yh1);
        }
        CLUSTER_SYNC();   // yh[par] complete in every CTA

        // v1 = vf(t1, yhat1) into vloc
        vf_eval(sm, tid, rank, t1, par, vW2);

        // einsum2: y += 0.5 * (s + v1.dx)
        if (tid < 64) {
            int bb = tid >> 4, hl = tid & 15;
            const float* vp = &sm->vloc[bb][hl * C_DIM];
            const float* dp = sm->dxv[bb];
            float a = 0.f;
            #pragma unroll
            for (int c = 0; c < C_DIM; c++) a += vp[c] * dp[c];
            y += 0.5f * (sdot + a);
        }
        __syncthreads();   // protect dxv/cury before next iteration writes
    }

    // ---- readout ----
    if (tid < 64) {
        int bb = tid >> 4, hl = tid & 15;
        sm->red[bb][hl] = y * rW[HSL * rank + hl];
    }
    __syncthreads();
    if (tid < BA) {
        float p = 0.f;
        #pragma unroll
        for (int hl = 0; hl < HSL; hl++) p += sm->red[tid][hl];
        uint32_t addr = s2u(&sm->pbuf[rank][tid]);
        st_cluster(addr, 0, p);   // gather at rank 0
    }
    CLUSTER_SYNC();
    if (rank == 0 && tid < BA) {
        float a = rb[0];
        #pragma unroll
        for (int r = 0; r < P_CL; r++) a += sm->pbuf[r][tid];
        out[b0 + tid] = a;
    }
    CLUSTER_SYNC();   // keep peer smem alive until all cluster traffic done
}

extern "C" void kernel_launch(void* const* d_in, const int* in_sizes, int n_in,
                              void* d_out, int out_size) {
    (void)in_sizes; (void)n_in; (void)out_size;
    const float* ts  = (const float*)d_in[0];
    const float* ys  = (const float*)d_in[1];
    const float* iW0 = (const float*)d_in[2];
    const float* ib0 = (const float*)d_in[3];
    const float* iW1 = (const float*)d_in[4];
    const float* ib1 = (const float*)d_in[5];
    const float* iW2 = (const float*)d_in[6];
    const float* ib2 = (const float*)d_in[7];
    const float* vW0 = (const float*)d_in[8];
    const float* vb0 = (const float*)d_in[9];
    const float* vW1 = (const float*)d_in[10];
    const float* vb1 = (const float*)d_in[11];
    const float* vW2 = (const float*)d_in[12];
    const float* vb2 = (const float*)d_in[13];
    const float* rW  = (const float*)d_in[14];
    const float* rb  = (const float*)d_in[15];
    float* out = (float*)d_out;

    cudaFuncSetAttribute(cde_kernel, cudaFuncAttributeMaxDynamicSharedMemorySize,
                         (int)sizeof(Smem));

    cde_transpose_kernel<<<(W_DIM * O_DIM + 255) / 256, 256>>>(vW2);
    cde_kernel<<<NCTA, NTHR, sizeof(Smem)>>>(
        ts, ys, iW0, ib0, iW1, ib1, iW2, ib2,
        vW0, vb0, vW1, vb1, vW2, vb2, rW, rb, out);
}